// round 4
// baseline (speedup 1.0000x reference)
#include <cuda_runtime.h>
#include <cuda_bf16.h>
#include <cstdint>

#define T_TOK 16384
#define D_DIM 1024
#define E_NUM 8
#define H_DIM 4096
#define CAP   (T_TOK / E_NUM)   // 2048
#define FIX_MAX 2048
#define GAP_THR 0.02f

// ---------------- scratch (device globals: allocation-free) ----------------
__device__ uint32_t g_xtf[(size_t)T_TOK * D_DIM];          // x as tf32       64MB
__device__ float    g_r[(size_t)T_TOK * D_DIM];            // router hidden   64MB
__device__ uint32_t g_h[(size_t)E_NUM * CAP * H_DIM];      // expert hid tf32 256MB
__device__ uint32_t g_wr1t[(size_t)D_DIM * D_DIM];         // wr1^T tf32      4MB
__device__ uint32_t g_w1t[(size_t)E_NUM * H_DIM * D_DIM];  // w1^T tf32       128MB
__device__ uint32_t g_w2t[(size_t)E_NUM * D_DIM * H_DIM];  // w2^T tf32       128MB
__device__ float    g_fixr[(size_t)FIX_MAX * D_DIM];       // exact r rows    8MB
__device__ int      g_fixlist[FIX_MAX];
__device__ int      g_fixcount;
__device__ int      g_eid[T_TOK];
__device__ float    g_gate[T_TOK];
__device__ int      g_idx[E_NUM * CAP];
__device__ float    g_gateslot[E_NUM * CAP];

// ---------------- helpers ----------------
__device__ __forceinline__ uint32_t f2tf32(float x) {
    uint32_t r;
    asm("cvt.rna.tf32.f32 %0, %1;" : "=r"(r) : "f"(x));
    return r;
}
__device__ __forceinline__ uint32_t smem_u32(const void* p) {
    uint32_t a;
    asm("{ .reg .u64 t; cvta.to.shared.u64 t, %1; cvt.u32.u64 %0, t; }"
        : "=r"(a) : "l"(p));
    return a;
}
__device__ __forceinline__ void cp_async16(uint32_t dst, const void* src, unsigned sz) {
    asm volatile("cp.async.cg.shared.global [%0], [%1], 16, %2;"
                 :: "r"(dst), "l"(src), "r"(sz) : "memory");
}
__device__ __forceinline__ void cp_commit() {
    asm volatile("cp.async.commit_group;" ::: "memory");
}
template <int N>
__device__ __forceinline__ void cp_wait() {
    asm volatile("cp.async.wait_group %0;" :: "n"(N) : "memory");
}

__device__ __forceinline__ void mma_tf32(float* d, const uint32_t* a, const uint32_t* b) {
    asm volatile(
        "mma.sync.aligned.m16n8k8.row.col.f32.tf32.tf32.f32 "
        "{%0,%1,%2,%3}, {%4,%5,%6,%7}, {%8,%9}, {%0,%1,%2,%3};"
        : "+f"(d[0]), "+f"(d[1]), "+f"(d[2]), "+f"(d[3])
        : "r"(a[0]), "r"(a[1]), "r"(a[2]), "r"(a[3]),
          "r"(b[0]), "r"(b[1]));
}

// ---------------- trivial kernels ----------------
__global__ void zero_out_kernel(float4* out, int n4) {
    int i = blockIdx.x * blockDim.x + threadIdx.x;
    if (i < n4) out[i] = make_float4(0.f, 0.f, 0.f, 0.f);
}

__global__ void init_kernel(int* idx, float* gs, int* fixlist, int* fixcount) {
    int i = blockIdx.x * blockDim.x + threadIdx.x;
    if (i < E_NUM * CAP) { idx[i] = T_TOK; gs[i] = 0.f; }
    if (i < FIX_MAX) fixlist[i] = T_TOK;
    if (i == 0) *fixcount = 0;
}

__global__ void cvt_x_kernel(const float4* __restrict__ x, uint4* __restrict__ xtf, int n4) {
    int i = blockIdx.x * blockDim.x + threadIdx.x;
    if (i < n4) {
        float4 v = x[i];
        uint4 t;
        t.x = f2tf32(v.x); t.y = f2tf32(v.y);
        t.z = f2tf32(v.z); t.w = f2tf32(v.w);
        xtf[i] = t;
    }
}

// in: [E][R][C] fp32 -> out: [E][C][R] tf32 bits
__global__ void transpose_tf32_kernel(const float* __restrict__ in,
                                      uint32_t* __restrict__ out, int R, int C)
{
    __shared__ uint32_t t[32][33];
    const float* ine  = in  + (size_t)blockIdx.z * R * C;
    uint32_t*    oute = out + (size_t)blockIdx.z * R * C;
    int c0 = blockIdx.x * 32, r0 = blockIdx.y * 32;
#pragma unroll
    for (int j = threadIdx.y; j < 32; j += 8)
        t[j][threadIdx.x] = f2tf32(ine[(size_t)(r0 + j) * C + c0 + threadIdx.x]);
    __syncthreads();
#pragma unroll
    for (int j = threadIdx.y; j < 32; j += 8)
        oute[(size_t)(c0 + j) * R + r0 + threadIdx.x] = t[threadIdx.x][j];
}

// ---------------- TF32 mma.sync GEMM, cp.async double-buffered ----------------
// C[M,N] = op(A[M,K] @ B[N,K]^T + bias[N]); A,B pre-converted tf32 bits.
// GATHER: A row m = A[idx[m]] (idx==T_TOK -> zero row)
// SCATTER: output row m -> Cout[idx[m]] * gate[m]; idx==T_TOK skipped
// OUT_TF32: store output as tf32 bits (relu'd hidden for next GEMM)
template<bool GATHER, bool RELU, bool SCATTER, bool OUT_TF32>
__global__ void __launch_bounds__(256, 2)
mma_gemm_kernel(const uint32_t* __restrict__ A, const uint32_t* __restrict__ B,
                const float* __restrict__ bias, uint32_t* __restrict__ Cout,
                int N, int K,
                const int* __restrict__ rowidx, const float* __restrict__ gates,
                size_t sA, size_t sB, size_t sBias, size_t sC)
{
    constexpr int BK = 32;
    constexpr int TILE_U32 = 128 * 36;               // stride-36 rows
    constexpr int TILE_B   = TILE_U32 * 4;           // 18432 bytes

    extern __shared__ char smem[];
    const uint32_t sbase = smem_u32(smem);
    int* sRow = (int*)smem;                           // [128]
    // buffers at 1024: A0,B0,A1,B1
    const uint32_t OFF_A[2] = {1024u, 1024u + 2 * TILE_B};
    const uint32_t OFF_B[2] = {1024u + TILE_B, 1024u + 3 * TILE_B};

    const int e = blockIdx.z;
    const uint32_t* Ae = A + (size_t)e * sA;
    const uint32_t* Be = B + (size_t)e * sB;
    const float*    be = bias + (size_t)e * sBias;
    uint32_t*       Ce = Cout + (size_t)e * sC;
    const int*   idxe = (GATHER || SCATTER) ? rowidx + e * CAP : nullptr;
    const float* gte  = SCATTER ? gates + e * CAP : nullptr;

    const int bm0 = blockIdx.y * 128;
    const int bn0 = blockIdx.x * 128;
    const int tid = threadIdx.x;
    const int warp = tid >> 5;
    const int lane = tid & 31;
    const int wr = warp >> 2;      // 0..1
    const int wc = warp & 3;       // 0..3
    const int lr = lane >> 2;      // 0..7
    const int lc = lane & 3;       // 0..3

    if (tid < 128)
        sRow[tid] = (GATHER || SCATTER) ? idxe[bm0 + tid] : (bm0 + tid);
    __syncthreads();

    const int row_f = tid >> 3;          // 0..31 is wrong; 256 threads -> tid>>3 = 0..31? no:
    // fill indexing: i = tid + l*256; row = i>>3 (0..127), kc = (i&7)*4
    auto fill = [&](int s, int step) {
        const int k0 = step * BK;
#pragma unroll
        for (int l = 0; l < 4; l++) {
            int i = tid + l * 256;
            int row = i >> 3;
            int kc  = (i & 7) * 4;
            uint32_t dstA = sbase + OFF_A[s] + (uint32_t)(row * 36 + kc) * 4;
            if (GATHER) {
                int src = sRow[row];
                bool ok = src < T_TOK;
                const uint32_t* gp = Ae + (size_t)(ok ? src : 0) * K + k0 + kc;
                cp_async16(dstA, gp, ok ? 16u : 0u);
            } else {
                cp_async16(dstA, Ae + (size_t)(bm0 + row) * K + k0 + kc, 16u);
            }
            uint32_t dstB = sbase + OFF_B[s] + (uint32_t)(row * 36 + kc) * 4;
            cp_async16(dstB, Be + (size_t)(bn0 + row) * K + k0 + kc, 16u);
        }
        cp_commit();
    };

    float acc[4][4][4];
#pragma unroll
    for (int mt = 0; mt < 4; mt++)
#pragma unroll
        for (int nt = 0; nt < 4; nt++)
#pragma unroll
            for (int i = 0; i < 4; i++) acc[mt][nt][i] = 0.f;

    const int KS = K / BK;
    fill(0, 0);

    for (int step = 0; step < KS; step++) {
        const int s = step & 1;
        if (step + 1 < KS) { fill(s ^ 1, step + 1); cp_wait<1>(); }
        else               { cp_wait<0>(); }
        __syncthreads();

        const uint32_t* As = (const uint32_t*)(smem + OFF_A[s]);
        const uint32_t* Bs = (const uint32_t*)(smem + OFF_B[s]);

#pragma unroll
        for (int kk = 0; kk < 4; kk++) {
            uint32_t a[4][4], b[4][2];
#pragma unroll
            for (int mt = 0; mt < 4; mt++) {
                const uint32_t* ap = As + (wr * 64 + mt * 16 + lr) * 36 + kk * 8 + lc;
                a[mt][0] = ap[0];
                a[mt][1] = ap[8 * 36];
                a[mt][2] = ap[4];
                a[mt][3] = ap[8 * 36 + 4];
            }
#pragma unroll
            for (int nt = 0; nt < 4; nt++) {
                const uint32_t* bp = Bs + (wc * 32 + nt * 8 + lr) * 36 + kk * 8 + lc;
                b[nt][0] = bp[0];
                b[nt][1] = bp[4];
            }
#pragma unroll
            for (int mt = 0; mt < 4; mt++)
#pragma unroll
                for (int nt = 0; nt < 4; nt++)
                    mma_tf32(acc[mt][nt], a[mt], b[nt]);
        }
        __syncthreads();
    }

    // ---- epilogue ----
#pragma unroll
    for (int nt = 0; nt < 4; nt++) {
        int cb = wc * 32 + nt * 8 + 2 * lc;
        float bv0 = be[bn0 + cb];
        float bv1 = be[bn0 + cb + 1];
#pragma unroll
        for (int mt = 0; mt < 4; mt++) {
#pragma unroll
            for (int h = 0; h < 2; h++) {
                int lm = wr * 64 + mt * 16 + lr + h * 8;
                float v0 = acc[mt][nt][h * 2 + 0] + bv0;
                float v1 = acc[mt][nt][h * 2 + 1] + bv1;
                if (RELU) { v0 = fmaxf(v0, 0.f); v1 = fmaxf(v1, 0.f); }
                uint32_t* dst;
                if (SCATTER) {
                    int token = sRow[lm];
                    if (token >= T_TOK) continue;
                    float g = gte[bm0 + lm];
                    v0 *= g; v1 *= g;
                    dst = Cout + (size_t)token * N + bn0 + cb;
                } else {
                    dst = Ce + (size_t)(bm0 + lm) * N + bn0 + cb;
                }
                uint2 o;
                if (OUT_TF32) { o.x = f2tf32(v0); o.y = f2tf32(v1); }
                else          { o.x = __float_as_uint(v0); o.y = __float_as_uint(v1); }
                *(uint2*)dst = o;
            }
        }
    }
}

// ---------------- exact fp32 SIMT GEMM for fixup (gathered rows) ----------------
// r_exact[slot] = relu(x[fixlist[slot]] @ wr1 + br1), slot-padded with T_TOK
__global__ void __launch_bounds__(256)
fix_sgemm_kernel(const float* __restrict__ A, const float* __restrict__ Bmat,
                 const float* __restrict__ bias, float* __restrict__ Cout,
                 const int* __restrict__ list, int N, int K)
{
    constexpr int BM = 128, BN = 128, BK = 16;
    const int bm0 = blockIdx.y * BM;
    const int bn0 = blockIdx.x * BN;
    const int tid = threadIdx.x;
    const int tx = tid & 15;
    const int ty = tid >> 4;

    if (list[bm0] >= T_TOK) return;   // whole block is padding

    __shared__ float As[BK][BM];
    __shared__ float Bs[BK][BN];
    __shared__ int   sRow[BM];
    if (tid < BM) sRow[tid] = list[bm0 + tid];
    __syncthreads();

    float acc[8][8];
#pragma unroll
    for (int i = 0; i < 8; i++)
#pragma unroll
        for (int j = 0; j < 8; j++) acc[i][j] = 0.f;

    for (int k0 = 0; k0 < K; k0 += BK) {
#pragma unroll
        for (int l = 0; l < 2; l++) {
            int i4  = tid + l * 256;
            int row = i4 >> 2;
            int c4  = (i4 & 3) * 4;
            int src = sRow[row];
            float4 v = (src < T_TOK)
                ? *(const float4*)(A + (size_t)src * K + k0 + c4)
                : make_float4(0.f, 0.f, 0.f, 0.f);
            As[c4 + 0][row] = v.x;
            As[c4 + 1][row] = v.y;
            As[c4 + 2][row] = v.z;
            As[c4 + 3][row] = v.w;
        }
#pragma unroll
        for (int l = 0; l < 2; l++) {
            int i4  = tid + l * 256;
            int row = i4 >> 5;
            int c4  = (i4 & 31) * 4;
            *(float4*)(&Bs[row][c4]) =
                *(const float4*)(Bmat + (size_t)(k0 + row) * N + bn0 + c4);
        }
        __syncthreads();
#pragma unroll
        for (int kk = 0; kk < BK; kk++) {
            float a[8], b[8];
            *(float4*)(a)     = *(const float4*)(&As[kk][ty * 8]);
            *(float4*)(a + 4) = *(const float4*)(&As[kk][ty * 8 + 4]);
            *(float4*)(b)     = *(const float4*)(&Bs[kk][tx * 8]);
            *(float4*)(b + 4) = *(const float4*)(&Bs[kk][tx * 8 + 4]);
#pragma unroll
            for (int i = 0; i < 8; i++)
#pragma unroll
                for (int j = 0; j < 8; j++)
                    acc[i][j] = fmaf(a[i], b[j], acc[i][j]);
        }
        __syncthreads();
    }

    float bv[8];
#pragma unroll
    for (int j = 0; j < 8; j++) bv[j] = bias[bn0 + tx * 8 + j];
#pragma unroll
    for (int i = 0; i < 8; i++) {
        float* dst = Cout + (size_t)(bm0 + ty * 8 + i) * N + bn0 + tx * 8;
        float o[8];
#pragma unroll
        for (int j = 0; j < 8; j++) o[j] = fmaxf(acc[i][j] + bv[j], 0.f);
        *(float4*)(dst)     = *(float4*)(o);
        *(float4*)(dst + 4) = *(float4*)(o + 4);
    }
}

// ---------------- router logits + gate + ambiguity flagging ----------------
__global__ void router_logits_kernel(const float* __restrict__ r,
                                     const float* __restrict__ wr2,
                                     const float* __restrict__ br2,
                                     int* __restrict__ eid,
                                     float* __restrict__ gate,
                                     int* __restrict__ fixlist,
                                     int* __restrict__ fixcount)
{
    int warp = threadIdx.x >> 5;
    int lane = threadIdx.x & 31;
    int t = blockIdx.x * (blockDim.x >> 5) + warp;
    if (t >= T_TOK) return;

    float acc[E_NUM];
#pragma unroll
    for (int e = 0; e < E_NUM; e++) acc[e] = 0.f;

    const float* row = r + (size_t)t * D_DIM;
    for (int k = lane; k < D_DIM; k += 32) {
        float rv = row[k];
        const float* w = wr2 + (size_t)k * E_NUM;
#pragma unroll
        for (int e = 0; e < E_NUM; e++) acc[e] = fmaf(rv, w[e], acc[e]);
    }
#pragma unroll
    for (int e = 0; e < E_NUM; e++) {
#pragma unroll
        for (int off = 16; off > 0; off >>= 1)
            acc[e] += __shfl_xor_sync(0xFFFFFFFFu, acc[e], off);
    }
    if (lane == 0) {
        float l[E_NUM];
        float m1 = -1e30f, m2 = -1e30f;
        int best = 0;
#pragma unroll
        for (int e = 0; e < E_NUM; e++) {
            l[e] = acc[e] + br2[e];
            if (l[e] > m1) { m2 = m1; m1 = l[e]; best = e; }
            else if (l[e] > m2) m2 = l[e];
        }
        float s = 0.f;
#pragma unroll
        for (int e = 0; e < E_NUM; e++) s += __expf(l[e] - m1);
        eid[t]  = best;
        gate[t] = 1.f / s;
        if (m1 - m2 < GAP_THR) {
            int slot = atomicAdd(fixcount, 1);
            if (slot < FIX_MAX) fixlist[slot] = t;
        }
    }
}

// exact logits for flagged tokens (overwrite eid/gate)
__global__ void fix_logits_kernel(const float* __restrict__ fixr,
                                  const int* __restrict__ fixlist,
                                  const float* __restrict__ wr2,
                                  const float* __restrict__ br2,
                                  int* __restrict__ eid,
                                  float* __restrict__ gate)
{
    int warp = threadIdx.x >> 5;
    int lane = threadIdx.x & 31;
    int slot = blockIdx.x * (blockDim.x >> 5) + warp;
    if (slot >= FIX_MAX) return;
    int t = fixlist[slot];
    if (t >= T_TOK) return;

    float acc[E_NUM];
#pragma unroll
    for (int e = 0; e < E_NUM; e++) acc[e] = 0.f;
    const float* row = fixr + (size_t)slot * D_DIM;
    for (int k = lane; k < D_DIM; k += 32) {
        float rv = row[k];
        const float* w = wr2 + (size_t)k * E_NUM;
#pragma unroll
        for (int e = 0; e < E_NUM; e++) acc[e] = fmaf(rv, w[e], acc[e]);
    }
#pragma unroll
    for (int e = 0; e < E_NUM; e++) {
#pragma unroll
        for (int off = 16; off > 0; off >>= 1)
            acc[e] += __shfl_xor_sync(0xFFFFFFFFu, acc[e], off);
    }
    if (lane == 0) {
        float l[E_NUM];
        float m1 = -1e30f;
        int best = 0;
#pragma unroll
        for (int e = 0; e < E_NUM; e++) {
            l[e] = acc[e] + br2[e];
            if (l[e] > m1) { m1 = l[e]; best = e; }
        }
        float s = 0.f;
#pragma unroll
        for (int e = 0; e < E_NUM; e++) s += __expf(l[e] - m1);
        eid[t]  = best;
        gate[t] = 1.f / s;
    }
}

// ---------------- capacity routing ----------------
__global__ void route_scan_kernel(const int* __restrict__ eid,
                                  const float* __restrict__ gate,
                                  int* __restrict__ idx,
                                  float* __restrict__ gateslot)
{
    const int e = blockIdx.x;
    const int tid = threadIdx.x;
    __shared__ int sc[256];
    int base = 0;
    for (int start = 0; start < T_TOK; start += 256) {
        int t = start + tid;
        int m = (eid[t] == e) ? 1 : 0;
        sc[tid] = m;
        __syncthreads();
#pragma unroll
        for (int off = 1; off < 256; off <<= 1) {
            int add = (tid >= off) ? sc[tid - off] : 0;
            __syncthreads();
            sc[tid] += add;
            __syncthreads();
        }
        int incl  = sc[tid];
        int total = sc[255];
        if (m) {
            int p = base + incl - 1;
            if (p < CAP) {
                idx[e * CAP + p]      = t;
                gateslot[e * CAP + p] = gate[t];
            }
        }
        base += total;
        __syncthreads();
    }
}

// ---------------- launch ----------------
extern "C" void kernel_launch(void* const* d_in, const int* in_sizes, int n_in,
                              void* d_out, int out_size)
{
    const float* x   = (const float*)d_in[0];
    const float* wr1 = (const float*)d_in[1];
    const float* br1 = (const float*)d_in[2];
    const float* wr2 = (const float*)d_in[3];
    const float* br2 = (const float*)d_in[4];
    const float* w1  = (const float*)d_in[5];
    const float* b1  = (const float*)d_in[6];
    const float* w2  = (const float*)d_in[7];
    const float* b2  = (const float*)d_in[8];
    float* out = (float*)d_out;

    uint32_t *xtf_ptr, *h_ptr, *wr1t_ptr, *w1t_ptr, *w2t_ptr;
    float *r_ptr, *gate_ptr, *gs_ptr, *fixr_ptr;
    int *eid_ptr, *idx_ptr, *fixlist_ptr, *fixcount_ptr;
    cudaGetSymbolAddress((void**)&xtf_ptr,     g_xtf);
    cudaGetSymbolAddress((void**)&r_ptr,       g_r);
    cudaGetSymbolAddress((void**)&h_ptr,       g_h);
    cudaGetSymbolAddress((void**)&wr1t_ptr,    g_wr1t);
    cudaGetSymbolAddress((void**)&w1t_ptr,     g_w1t);
    cudaGetSymbolAddress((void**)&w2t_ptr,     g_w2t);
    cudaGetSymbolAddress((void**)&fixr_ptr,    g_fixr);
    cudaGetSymbolAddress((void**)&fixlist_ptr, g_fixlist);
    cudaGetSymbolAddress((void**)&fixcount_ptr,g_fixcount);
    cudaGetSymbolAddress((void**)&gate_ptr,    g_gate);
    cudaGetSymbolAddress((void**)&gs_ptr,      g_gateslot);
    cudaGetSymbolAddress((void**)&eid_ptr,     g_eid);
    cudaGetSymbolAddress((void**)&idx_ptr,     g_idx);

    constexpr int SMEM_BYTES = 1024 + 4 * (128 * 36 * 4);  // 74752
    cudaFuncSetAttribute(mma_gemm_kernel<false, true, false, false>,
                         cudaFuncAttributeMaxDynamicSharedMemorySize, SMEM_BYTES);
    cudaFuncSetAttribute(mma_gemm_kernel<true, true, false, true>,
                         cudaFuncAttributeMaxDynamicSharedMemorySize, SMEM_BYTES);
    cudaFuncSetAttribute(mma_gemm_kernel<false, false, true, false>,
                         cudaFuncAttributeMaxDynamicSharedMemorySize, SMEM_BYTES);

    // 1) zero output
    {
        int n4 = ((size_t)T_TOK * D_DIM) / 4;
        zero_out_kernel<<<(n4 + 255) / 256, 256>>>((float4*)out, n4);
    }
    // 2) init (idx, gateslot, fixlist, fixcount)
    init_kernel<<<(E_NUM * CAP + 255) / 256, 256>>>(idx_ptr, gs_ptr, fixlist_ptr, fixcount_ptr);
    // 3) x -> tf32
    {
        int n4 = ((size_t)T_TOK * D_DIM) / 4;
        cvt_x_kernel<<<(n4 + 255) / 256, 256>>>((const float4*)x, (uint4*)xtf_ptr, n4);
    }
    // 4) wr1 transpose+cvt
    {
        dim3 blk(32, 8);
        dim3 g(D_DIM / 32, D_DIM / 32, 1);
        transpose_tf32_kernel<<<g, blk>>>(wr1, wr1t_ptr, D_DIM, D_DIM);
    }
    // 5) w1 transpose+cvt: [E][D][H] -> [E][H][D]
    {
        dim3 blk(32, 8);
        dim3 g(H_DIM / 32, D_DIM / 32, E_NUM);
        transpose_tf32_kernel<<<g, blk>>>(w1, w1t_ptr, D_DIM, H_DIM);
    }
    // 6) router GEMM (tf32): r = relu(x @ wr1 + br1)   <- profiled launch
    {
        dim3 grid(D_DIM / 128, T_TOK / 128, 1);
        mma_gemm_kernel<false, true, false, false><<<grid, 256, SMEM_BYTES>>>(
            xtf_ptr, wr1t_ptr, br1, (uint32_t*)r_ptr, D_DIM, D_DIM,
            nullptr, nullptr, 0, 0, 0, 0);
    }
    // 7) logits + gate + flag ambiguous
    router_logits_kernel<<<T_TOK / 8, 256>>>(r_ptr, wr2, br2, eid_ptr, gate_ptr,
                                             fixlist_ptr, fixcount_ptr);
    // 8) exact r rows for flagged tokens (early-exit blocks)
    {
        dim3 grid(D_DIM / 128, FIX_MAX / 128, 1);
        fix_sgemm_kernel<<<grid, 256>>>(x, wr1, br1, fixr_ptr, fixlist_ptr, D_DIM, D_DIM);
    }
    // 9) exact logits overwrite for flagged tokens
    fix_logits_kernel<<<FIX_MAX / 8, 256>>>(fixr_ptr, fixlist_ptr, wr2, br2,
                                            eid_ptr, gate_ptr);
    // 10) routing scan
    route_scan_kernel<<<E_NUM, 256>>>(eid_ptr, gate_ptr, idx_ptr, gs_ptr);
    // 11) w2 transpose+cvt: [E][H][D] -> [E][D][H]
    {
        dim3 blk(32, 8);
        dim3 g(D_DIM / 32, H_DIM / 32, E_NUM);
        transpose_tf32_kernel<<<g, blk>>>(w2, w2t_ptr, H_DIM, D_DIM);
    }
    // 12) h = relu(gather(x) @ w1 + b1)  (stored tf32)
    {
        dim3 grid(H_DIM / 128, CAP / 128, E_NUM);
        mma_gemm_kernel<true, true, false, true><<<grid, 256, SMEM_BYTES>>>(
            xtf_ptr, w1t_ptr, b1, h_ptr, H_DIM, D_DIM,
            idx_ptr, nullptr,
            0, (size_t)H_DIM * D_DIM, H_DIM, (size_t)CAP * H_DIM);
    }
    // 13) out[idx] = gate * (h @ w2 + b2)
    {
        dim3 grid(D_DIM / 128, CAP / 128, E_NUM);
        mma_gemm_kernel<false, false, true, false><<<grid, 256, SMEM_BYTES>>>(
            h_ptr, w2t_ptr, b2, (uint32_t*)out, D_DIM, H_DIM,
            idx_ptr, gs_ptr,
            (size_t)CAP * H_DIM, (size_t)D_DIM * H_DIM, D_DIM, 0);
    }
}

// round 5
// speedup vs baseline: 1.2210x; 1.2210x over previous
#include <cuda_runtime.h>
#include <cuda_bf16.h>
#include <cstdint>

#define T_TOK 16384
#define D_DIM 1024
#define E_NUM 8
#define H_DIM 4096
#define CAP   (T_TOK / E_NUM)   // 2048
#define FIX_MAX 2048
#define GAP_THR 0.02f

// ---------------- scratch (device globals: allocation-free) ----------------
__device__ float g_r[(size_t)T_TOK * D_DIM];          // relu(x@wr1+br1)   64MB
__device__ float g_h[(size_t)E_NUM * CAP * H_DIM];    // expert hidden    256MB
__device__ float g_fixlogit[FIX_MAX * E_NUM];
__device__ int   g_fixlist[FIX_MAX];
__device__ int   g_fixcount;
__device__ int   g_eid[T_TOK];
__device__ float g_gate[T_TOK];
__device__ int   g_idx[E_NUM * CAP];
__device__ float g_gateslot[E_NUM * CAP];

// ---------------- helpers ----------------
__device__ __forceinline__ uint32_t f2tf32(float x) {
    uint32_t r;
    asm("cvt.rna.tf32.f32 %0, %1;" : "=r"(r) : "f"(x));
    return r;
}
__device__ __forceinline__ void mma_tf32(float* d,
                                         const uint32_t* a, const uint32_t* b) {
    asm volatile(
        "mma.sync.aligned.m16n8k8.row.col.f32.tf32.tf32.f32 "
        "{%0,%1,%2,%3}, {%4,%5,%6,%7}, {%8,%9}, {%0,%1,%2,%3};"
        : "+f"(d[0]), "+f"(d[1]), "+f"(d[2]), "+f"(d[3])
        : "r"(a[0]), "r"(a[1]), "r"(a[2]), "r"(a[3]),
          "r"(b[0]), "r"(b[1]));
}

// ---------------- zero/init (single kernel) ----------------
__global__ void zeroinit_kernel(float4* out, int n4, int* idx, float* gs,
                                int* fixlist, int* fixcount, float* fixlogit) {
    int i = blockIdx.x * blockDim.x + threadIdx.x;
    if (i < n4) out[i] = make_float4(0.f, 0.f, 0.f, 0.f);
    if (i < E_NUM * CAP) { idx[i] = T_TOK; gs[i] = 0.f; }
    if (i < FIX_MAX) fixlist[i] = T_TOK;
    if (i < FIX_MAX * E_NUM) fixlogit[i] = 0.f;
    if (i == 0) *fixcount = 0;
}

// ---------------- TF32 tensor-core GEMM (round-2 proven kernel) ----------------
// C[M,N] = op(A[M,K] @ B[K,N] + bias[N]), fp32 in/out, tf32 compute.
// GATHER:  A row m is A[idx[m]] (idx==T_TOK -> zero row)
// SCATTER: output row m goes to Cout[idx[m]]*gate[m]; idx==T_TOK skipped
template<bool GATHER, bool RELU, bool SCATTER>
__global__ void __launch_bounds__(256)
tf32gemm_kernel(const float* __restrict__ A, const float* __restrict__ Bmat,
                const float* __restrict__ bias, float* __restrict__ Cout,
                int M, int N, int K,
                const int* __restrict__ rowidx, const float* __restrict__ gates,
                size_t sA, size_t sB, size_t sBias, size_t sC)
{
    constexpr int BM = 128, BN = 128, BK = 32;

    const int e = blockIdx.z;
    const float* Ae   = A    + (size_t)e * sA;
    const float* Be   = Bmat + (size_t)e * sB;
    const float* be   = bias + (size_t)e * sBias;
    float*       Ce   = Cout + (size_t)e * sC;
    const int*   idxe = (GATHER || SCATTER) ? rowidx + e * CAP : nullptr;
    const float* gte  = SCATTER ? gates + e * CAP : nullptr;

    const int bm0 = blockIdx.y * BM;
    const int bn0 = blockIdx.x * BN;
    const int tid = threadIdx.x;
    const int warp = tid >> 5;
    const int lane = tid & 31;
    const int wr = warp >> 2;      // 0..1  (64-row slabs)
    const int wc = warp & 3;       // 0..3  (32-col slabs)
    const int lr = lane >> 2;      // 0..7
    const int lc = lane & 3;       // 0..3

    __shared__ uint32_t As[BM][BK + 4];    // bank=(4m+k)%32 -> conflict-free
    __shared__ uint32_t Bs[BK][BN + 8];    // bank=(8k+n)%32 -> conflict-free
    __shared__ int      sRow[BM];

    if (tid < BM) {
        sRow[tid] = (GATHER || SCATTER) ? idxe[bm0 + tid] : (bm0 + tid);
    }
    __syncthreads();

    float acc[4][4][4];
#pragma unroll
    for (int mt = 0; mt < 4; mt++)
#pragma unroll
        for (int nt = 0; nt < 4; nt++)
#pragma unroll
            for (int i = 0; i < 4; i++) acc[mt][nt][i] = 0.f;

    for (int k0 = 0; k0 < K; k0 += BK) {
        // ---- A tile: 128 x 32 fp32 -> tf32 smem ----
#pragma unroll
        for (int l = 0; l < 4; l++) {
            int i4  = tid + l * 256;            // 0..1023
            int row = i4 >> 3;                  // 0..127
            int c4  = (i4 & 7) * 4;             // 0,4,...,28
            float4 v;
            if (GATHER) {
                int src = sRow[row];
                if (src >= T_TOK) v = make_float4(0.f, 0.f, 0.f, 0.f);
                else v = *(const float4*)(Ae + (size_t)src * K + k0 + c4);
            } else {
                v = *(const float4*)(Ae + (size_t)(bm0 + row) * K + k0 + c4);
            }
            uint4 t;
            t.x = f2tf32(v.x); t.y = f2tf32(v.y);
            t.z = f2tf32(v.z); t.w = f2tf32(v.w);
            *(uint4*)&As[row][c4] = t;
        }
        // ---- B tile: 32 x 128 fp32 -> tf32 smem ----
#pragma unroll
        for (int l = 0; l < 4; l++) {
            int i4  = tid + l * 256;
            int row = i4 >> 5;                  // 0..31
            int c4  = (i4 & 31) * 4;            // 0..124
            float4 v = *(const float4*)(Be + (size_t)(k0 + row) * N + bn0 + c4);
            uint4 t;
            t.x = f2tf32(v.x); t.y = f2tf32(v.y);
            t.z = f2tf32(v.z); t.w = f2tf32(v.w);
            *(uint4*)&Bs[row][c4] = t;
        }
        __syncthreads();

#pragma unroll
        for (int kk = 0; kk < BK; kk += 8) {
            uint32_t a[4][4], b[4][2];
#pragma unroll
            for (int mt = 0; mt < 4; mt++) {
                int m0 = wr * 64 + mt * 16;
                a[mt][0] = As[m0 + lr    ][kk + lc    ];
                a[mt][1] = As[m0 + lr + 8][kk + lc    ];
                a[mt][2] = As[m0 + lr    ][kk + lc + 4];
                a[mt][3] = As[m0 + lr + 8][kk + lc + 4];
            }
#pragma unroll
            for (int nt = 0; nt < 4; nt++) {
                int n0 = wc * 32 + nt * 8;
                b[nt][0] = Bs[kk + lc    ][n0 + lr];
                b[nt][1] = Bs[kk + lc + 4][n0 + lr];
            }
#pragma unroll
            for (int mt = 0; mt < 4; mt++)
#pragma unroll
                for (int nt = 0; nt < 4; nt++)
                    mma_tf32(acc[mt][nt], a[mt], b[nt]);
        }
        __syncthreads();
    }

    // ---- epilogue ----
#pragma unroll
    for (int nt = 0; nt < 4; nt++) {
        int cb = wc * 32 + nt * 8 + 2 * lc;
        float bv0 = be[bn0 + cb];
        float bv1 = be[bn0 + cb + 1];
#pragma unroll
        for (int mt = 0; mt < 4; mt++) {
#pragma unroll
            for (int h = 0; h < 2; h++) {
                int lm = wr * 64 + mt * 16 + lr + h * 8;
                float v0 = acc[mt][nt][h * 2 + 0] + bv0;
                float v1 = acc[mt][nt][h * 2 + 1] + bv1;
                if (RELU) { v0 = fmaxf(v0, 0.f); v1 = fmaxf(v1, 0.f); }
                float* dst;
                if (SCATTER) {
                    int token = sRow[lm];
                    if (token >= T_TOK) continue;
                    float g = gte[bm0 + lm];
                    v0 *= g; v1 *= g;
                    dst = Cout + (size_t)token * N + bn0 + cb;
                } else {
                    dst = Ce + (size_t)(bm0 + lm) * N + bn0 + cb;
                }
                *(float2*)dst = make_float2(v0, v1);
            }
        }
    }
}

// ---------------- router logits + gate + ambiguity flagging ----------------
__global__ void router_logits_kernel(const float* __restrict__ r,
                                     const float* __restrict__ wr2,
                                     const float* __restrict__ br2,
                                     int* __restrict__ eid,
                                     float* __restrict__ gate,
                                     int* __restrict__ fixlist,
                                     int* __restrict__ fixcount)
{
    int warp = threadIdx.x >> 5;
    int lane = threadIdx.x & 31;
    int t = blockIdx.x * (blockDim.x >> 5) + warp;
    if (t >= T_TOK) return;

    float acc[E_NUM];
#pragma unroll
    for (int e = 0; e < E_NUM; e++) acc[e] = 0.f;

    const float* row = r + (size_t)t * D_DIM;
    for (int k = lane; k < D_DIM; k += 32) {
        float rv = row[k];
        const float* w = wr2 + (size_t)k * E_NUM;
#pragma unroll
        for (int e = 0; e < E_NUM; e++) acc[e] = fmaf(rv, w[e], acc[e]);
    }
#pragma unroll
    for (int e = 0; e < E_NUM; e++) {
#pragma unroll
        for (int off = 16; off > 0; off >>= 1)
            acc[e] += __shfl_xor_sync(0xFFFFFFFFu, acc[e], off);
    }
    if (lane == 0) {
        float l[E_NUM];
        float m1 = -1e30f, m2 = -1e30f;
        int best = 0;
#pragma unroll
        for (int e = 0; e < E_NUM; e++) {
            l[e] = acc[e] + br2[e];
            if (l[e] > m1) { m2 = m1; m1 = l[e]; best = e; }
            else if (l[e] > m2) m2 = l[e];
        }
        float s = 0.f;
#pragma unroll
        for (int e = 0; e < E_NUM; e++) s += __expf(l[e] - m1);
        eid[t]  = best;
        gate[t] = 1.f / s;
        if (m1 - m2 < GAP_THR) {
            int slot = atomicAdd(fixcount, 1);
            if (slot < FIX_MAX) fixlist[slot] = t;
        }
    }
}

// ---------------- exact fp32 fixup GEMM -> partial logits (atomicAdd) ----------------
// For flagged tokens: r_row = relu(x[t] @ wr1 + br1) per 128-col tile,
// then fixlogit[slot][e] += r_tile @ wr2[tile_cols].
__global__ void __launch_bounds__(256)
fix_gemm_kernel(const float* __restrict__ A, const float* __restrict__ Bmat,
                const float* __restrict__ bias, const float* __restrict__ wr2,
                const int* __restrict__ list, float* __restrict__ fixlogit,
                int N, int K)
{
    constexpr int BM = 128, BN = 128, BK = 16;
    const int bm0 = blockIdx.y * BM;
    const int bn0 = blockIdx.x * BN;
    const int tid = threadIdx.x;
    const int tx = tid & 15;
    const int ty = tid >> 4;

    if (list[bm0] >= T_TOK) return;   // whole block is padding

    __shared__ float As[BK][BM];
    __shared__ float Bs[BK][BN];
    __shared__ int   sRow[BM];
    if (tid < BM) sRow[tid] = list[bm0 + tid];
    __syncthreads();

    float acc[8][8];
#pragma unroll
    for (int i = 0; i < 8; i++)
#pragma unroll
        for (int j = 0; j < 8; j++) acc[i][j] = 0.f;

    for (int k0 = 0; k0 < K; k0 += BK) {
#pragma unroll
        for (int l = 0; l < 2; l++) {
            int i4  = tid + l * 256;
            int row = i4 >> 2;
            int c4  = (i4 & 3) * 4;
            int src = sRow[row];
            float4 v = (src < T_TOK)
                ? *(const float4*)(A + (size_t)src * K + k0 + c4)
                : make_float4(0.f, 0.f, 0.f, 0.f);
            As[c4 + 0][row] = v.x;
            As[c4 + 1][row] = v.y;
            As[c4 + 2][row] = v.z;
            As[c4 + 3][row] = v.w;
        }
#pragma unroll
        for (int l = 0; l < 2; l++) {
            int i4  = tid + l * 256;
            int row = i4 >> 5;
            int c4  = (i4 & 31) * 4;
            *(float4*)(&Bs[row][c4]) =
                *(const float4*)(Bmat + (size_t)(k0 + row) * N + bn0 + c4);
        }
        __syncthreads();
#pragma unroll
        for (int kk = 0; kk < BK; kk++) {
            float a[8], b[8];
            *(float4*)(a)     = *(const float4*)(&As[kk][ty * 8]);
            *(float4*)(a + 4) = *(const float4*)(&As[kk][ty * 8 + 4]);
            *(float4*)(b)     = *(const float4*)(&Bs[kk][tx * 8]);
            *(float4*)(b + 4) = *(const float4*)(&Bs[kk][tx * 8 + 4]);
#pragma unroll
            for (int i = 0; i < 8; i++)
#pragma unroll
                for (int j = 0; j < 8; j++)
                    acc[i][j] = fmaf(a[i], b[j], acc[i][j]);
        }
        __syncthreads();
    }

    // bias + relu, then partial logits for this col-slice via wr2
    float bv[8];
#pragma unroll
    for (int j = 0; j < 8; j++) bv[j] = bias[bn0 + tx * 8 + j];

    // load wr2 rows for our 8 columns: wr2[(bn0+tx*8+j)][e], e=0..7
    float w2r[8][8];
#pragma unroll
    for (int j = 0; j < 8; j++) {
        const float* wrow = wr2 + (size_t)(bn0 + tx * 8 + j) * E_NUM;
        *(float4*)(&w2r[j][0]) = *(const float4*)(wrow);
        *(float4*)(&w2r[j][4]) = *(const float4*)(wrow + 4);
    }

#pragma unroll
    for (int i = 0; i < 8; i++) {
        int slot = bm0 + ty * 8 + i;
        if (sRow[ty * 8 + i] >= T_TOK) continue;
        float o[8];
#pragma unroll
        for (int j = 0; j < 8; j++) o[j] = fmaxf(acc[i][j] + bv[j], 0.f);
        float pl[E_NUM];
#pragma unroll
        for (int e = 0; e < E_NUM; e++) pl[e] = 0.f;
#pragma unroll
        for (int j = 0; j < 8; j++)
#pragma unroll
            for (int e = 0; e < E_NUM; e++)
                pl[e] = fmaf(o[j], w2r[j][e], pl[e]);
#pragma unroll
        for (int e = 0; e < E_NUM; e++)
            atomicAdd(&fixlogit[slot * E_NUM + e], pl[e]);
    }
}

// ---------------- capacity routing (applies fixups first) ----------------
__global__ void route_scan_kernel(const float* __restrict__ fixlogit,
                                  const int* __restrict__ fixlist,
                                  const float* __restrict__ br2,
                                  int* __restrict__ eid,
                                  float* __restrict__ gate,
                                  int* __restrict__ idx,
                                  float* __restrict__ gateslot)
{
    const int e = blockIdx.x;
    const int tid = threadIdx.x;

    // phase 0: apply exact-logit corrections (all blocks write identical values)
    for (int s = tid; s < FIX_MAX; s += 256) {
        int t = fixlist[s];
        if (t >= T_TOK) continue;
        float l[E_NUM];
        float m1 = -1e30f;
        int best = 0;
#pragma unroll
        for (int q = 0; q < E_NUM; q++) {
            l[q] = fixlogit[s * E_NUM + q] + br2[q];
            if (l[q] > m1) { m1 = l[q]; best = q; }
        }
        float sum = 0.f;
#pragma unroll
        for (int q = 0; q < E_NUM; q++) sum += __expf(l[q] - m1);
        eid[t]  = best;
        gate[t] = 1.f / sum;
    }
    __syncthreads();

    // phase 1: token-ordered prefix scan for this expert
    __shared__ int sc[256];
    int base = 0;
    for (int start = 0; start < T_TOK; start += 256) {
        int t = start + tid;
        int m = (eid[t] == e) ? 1 : 0;
        sc[tid] = m;
        __syncthreads();
#pragma unroll
        for (int off = 1; off < 256; off <<= 1) {
            int add = (tid >= off) ? sc[tid - off] : 0;
            __syncthreads();
            sc[tid] += add;
            __syncthreads();
        }
        int incl  = sc[tid];
        int total = sc[255];
        if (m) {
            int p = base + incl - 1;
            if (p < CAP) {
                idx[e * CAP + p]      = t;
                gateslot[e * CAP + p] = gate[t];
            }
        }
        base += total;
        __syncthreads();
    }
}

// ---------------- launch ----------------
extern "C" void kernel_launch(void* const* d_in, const int* in_sizes, int n_in,
                              void* d_out, int out_size)
{
    const float* x   = (const float*)d_in[0];
    const float* wr1 = (const float*)d_in[1];
    const float* br1 = (const float*)d_in[2];
    const float* wr2 = (const float*)d_in[3];
    const float* br2 = (const float*)d_in[4];
    const float* w1  = (const float*)d_in[5];
    const float* b1  = (const float*)d_in[6];
    const float* w2  = (const float*)d_in[7];
    const float* b2  = (const float*)d_in[8];
    float* out = (float*)d_out;

    float *r_ptr, *h_ptr, *gate_ptr, *gs_ptr, *fixlogit_ptr;
    int *eid_ptr, *idx_ptr, *fixlist_ptr, *fixcount_ptr;
    cudaGetSymbolAddress((void**)&r_ptr,        g_r);
    cudaGetSymbolAddress((void**)&h_ptr,        g_h);
    cudaGetSymbolAddress((void**)&fixlogit_ptr, g_fixlogit);
    cudaGetSymbolAddress((void**)&fixlist_ptr,  g_fixlist);
    cudaGetSymbolAddress((void**)&fixcount_ptr, g_fixcount);
    cudaGetSymbolAddress((void**)&gate_ptr,     g_gate);
    cudaGetSymbolAddress((void**)&gs_ptr,       g_gateslot);
    cudaGetSymbolAddress((void**)&eid_ptr,      g_eid);
    cudaGetSymbolAddress((void**)&idx_ptr,      g_idx);

    // 1) zero output + init routing state
    {
        int n4 = ((size_t)T_TOK * D_DIM) / 4;
        zeroinit_kernel<<<(n4 + 255) / 256, 256>>>(
            (float4*)out, n4, idx_ptr, gs_ptr, fixlist_ptr, fixcount_ptr, fixlogit_ptr);
    }

    // 2) r = relu(x @ wr1 + br1)   -- tf32 tensor cores
    {
        dim3 grid(D_DIM / 128, T_TOK / 128, 1);
        tf32gemm_kernel<false, true, false><<<grid, 256>>>(
            x, wr1, br1, r_ptr, T_TOK, D_DIM, D_DIM,
            nullptr, nullptr, 0, 0, 0, 0);
    }

    // 3) logits -> eid, gate, flag ambiguous tokens
    router_logits_kernel<<<T_TOK / 8, 256>>>(r_ptr, wr2, br2, eid_ptr, gate_ptr,
                                             fixlist_ptr, fixcount_ptr);

    // 4) exact fp32 partial logits for flagged tokens
    {
        dim3 grid(D_DIM / 128, FIX_MAX / 128, 1);
        fix_gemm_kernel<<<grid, 256>>>(x, wr1, br1, wr2, fixlist_ptr,
                                       fixlogit_ptr, D_DIM, D_DIM);
    }

    // 5) apply fixups + routing scan
    route_scan_kernel<<<E_NUM, 256>>>(fixlogit_ptr, fixlist_ptr, br2,
                                      eid_ptr, gate_ptr, idx_ptr, gs_ptr);

    // 6) h[e] = relu(gather(x, idx[e]) @ w1[e] + b1[e])   -- tf32 (profiled)
    {
        dim3 grid(H_DIM / 128, CAP / 128, E_NUM);
        tf32gemm_kernel<true, true, false><<<grid, 256>>>(
            x, w1, b1, h_ptr, CAP, H_DIM, D_DIM,
            idx_ptr, nullptr,
            0, (size_t)D_DIM * H_DIM, H_DIM, (size_t)CAP * H_DIM);
    }

    // 7) out[idx] = gate * (h[e] @ w2[e] + b2[e])   -- tf32
    {
        dim3 grid(D_DIM / 128, CAP / 128, E_NUM);
        tf32gemm_kernel<false, false, true><<<grid, 256>>>(
            h_ptr, w2, b2, out, CAP, D_DIM, H_DIM,
            idx_ptr, gs_ptr,
            (size_t)CAP * H_DIM, (size_t)H_DIM * D_DIM, D_DIM, 0);
    }
}

// round 6
// speedup vs baseline: 1.8847x; 1.5436x over previous
#include <cuda_runtime.h>
#include <cuda_fp16.h>
#include <cstdint>

#define T_TOK 16384
#define D_DIM 1024
#define E_NUM 8
#define H_DIM 4096
#define CAP   (T_TOK / E_NUM)   // 2048
#define FIX_MAX 2048
#define GAP_THR 0.02f

// ---------------- scratch (device globals: allocation-free) ----------------
__device__ float g_r[(size_t)T_TOK * D_DIM];          // relu(x@wr1+br1)   64MB
__device__ float g_h[(size_t)E_NUM * CAP * H_DIM];    // expert hidden    256MB
__device__ float g_fixlogit[FIX_MAX * E_NUM];
__device__ int   g_fixlist[FIX_MAX];
__device__ int   g_fixcount;
__device__ int   g_eid[T_TOK];
__device__ float g_gate[T_TOK];
__device__ int   g_idx[E_NUM * CAP];
__device__ float g_gateslot[E_NUM * CAP];

// ---------------- helpers ----------------
__device__ __forceinline__ uint32_t pack_h2(float a, float b) {
    __half2 h = __floats2half2_rn(a, b);
    return *(uint32_t*)&h;
}
__device__ __forceinline__ void mma_f16(float* d, const uint32_t* a,
                                        const uint32_t* b) {
    asm volatile(
        "mma.sync.aligned.m16n8k16.row.col.f32.f16.f16.f32 "
        "{%0,%1,%2,%3}, {%4,%5,%6,%7}, {%8,%9}, {%0,%1,%2,%3};"
        : "+f"(d[0]), "+f"(d[1]), "+f"(d[2]), "+f"(d[3])
        : "r"(a[0]), "r"(a[1]), "r"(a[2]), "r"(a[3]),
          "r"(b[0]), "r"(b[1]));
}

// ---------------- zero/init ----------------
__global__ void zeroinit_kernel(float4* out, int n4, int* idx, float* gs,
                                int* fixlist, int* fixcount, float* fixlogit) {
    int i = blockIdx.x * blockDim.x + threadIdx.x;
    if (i < n4) out[i] = make_float4(0.f, 0.f, 0.f, 0.f);
    if (i < E_NUM * CAP) { idx[i] = T_TOK; gs[i] = 0.f; }
    if (i < FIX_MAX) fixlist[i] = T_TOK;
    if (i < FIX_MAX * E_NUM) fixlogit[i] = 0.f;
    if (i == 0) *fixcount = 0;
}

// ---------------- FP16 tensor-core GEMM (m16n8k16, fp32 accum) ----------------
// C[M,N] = op(A[M,K] @ B[K,N] + bias[N]), fp32 in/out, fp16 compute.
// GATHER:  A row m is A[idx[m]] (idx==T_TOK -> zero row)
// SCATTER: output row m goes to Cout[idx[m]]*gate[m]; idx==T_TOK skipped
template<bool GATHER, bool RELU, bool SCATTER>
__global__ void __launch_bounds__(256)
h16gemm_kernel(const float* __restrict__ A, const float* __restrict__ Bmat,
               const float* __restrict__ bias, float* __restrict__ Cout,
               int N, int K,
               const int* __restrict__ rowidx, const float* __restrict__ gates,
               size_t sA, size_t sB, size_t sBias, size_t sC)
{
    constexpr int BM = 128, BN = 128, BK = 32;
    constexpr int KH = BK / 2;               // 16 k-pairs

    const int e = blockIdx.z;
    const float* Ae   = A    + (size_t)e * sA;
    const float* Be   = Bmat + (size_t)e * sB;
    const float* be   = bias + (size_t)e * sBias;
    float*       Ce   = Cout + (size_t)e * sC;
    const int*   idxe = (GATHER || SCATTER) ? rowidx + e * CAP : nullptr;
    const float* gte  = SCATTER ? gates + e * CAP : nullptr;

    const int bm0 = blockIdx.y * BM;
    const int bn0 = blockIdx.x * BN;
    const int tid = threadIdx.x;
    const int warp = tid >> 5;
    const int lane = tid & 31;
    const int wr = warp >> 2;      // 0..1  (64-row slabs)
    const int wc = warp & 3;       // 0..3  (32-col slabs)
    const int lr = lane >> 2;      // 0..7  (groupID)
    const int lc = lane & 3;       // 0..3  (threadID-in-group)

    // As[m][kh]: k-pair kh of row m. stride 20 words -> bank (20m+kh)%32 conflict-free
    __shared__ uint32_t As[BM][KH + 4];
    // Bs[kh][n]: half2(B[2kh][n], B[2kh+1][n]). stride 136 -> bank (8kh+n)%32 conflict-free
    __shared__ uint32_t Bs[KH][BN + 8];
    __shared__ int      sRow[BM];

    if (tid < BM) {
        sRow[tid] = (GATHER || SCATTER) ? idxe[bm0 + tid] : (bm0 + tid);
    }
    __syncthreads();

    float acc[4][4][4];
#pragma unroll
    for (int mt = 0; mt < 4; mt++)
#pragma unroll
        for (int nt = 0; nt < 4; nt++)
#pragma unroll
            for (int i = 0; i < 4; i++) acc[mt][nt][i] = 0.f;

    for (int k0 = 0; k0 < K; k0 += BK) {
        // ---- A tile: 128 rows x 32 k (fp32 -> half2 pairs) ----
#pragma unroll
        for (int l = 0; l < 2; l++) {
            int i = tid + l * 256;              // 0..511
            int row = i >> 2;                   // 0..127
            int kq  = (i & 3) * 4;              // kh base: 0,4,8,12
            float4 v0, v1;
            if (GATHER) {
                int src = sRow[row];
                if (src >= T_TOK) {
                    v0 = make_float4(0.f, 0.f, 0.f, 0.f);
                    v1 = v0;
                } else {
                    const float* p = Ae + (size_t)src * K + k0 + kq * 2;
                    v0 = *(const float4*)(p);
                    v1 = *(const float4*)(p + 4);
                }
            } else {
                const float* p = Ae + (size_t)(bm0 + row) * K + k0 + kq * 2;
                v0 = *(const float4*)(p);
                v1 = *(const float4*)(p + 4);
            }
            uint4 t;
            t.x = pack_h2(v0.x, v0.y);
            t.y = pack_h2(v0.z, v0.w);
            t.z = pack_h2(v1.x, v1.y);
            t.w = pack_h2(v1.z, v1.w);
            *(uint4*)&As[row][kq] = t;
        }
        // ---- B tile: 32 k x 128 n, pack k-pairs ----
#pragma unroll
        for (int l = 0; l < 2; l++) {
            int i = tid + l * 256;              // 0..511
            int kh = i >> 5;                    // 0..15
            int c4 = (i & 31) * 4;              // 0..124
            const float* p0 = Be + (size_t)(k0 + 2 * kh)     * N + bn0 + c4;
            const float* p1 = Be + (size_t)(k0 + 2 * kh + 1) * N + bn0 + c4;
            float4 r0 = *(const float4*)p0;
            float4 r1 = *(const float4*)p1;
            uint4 t;
            t.x = pack_h2(r0.x, r1.x);
            t.y = pack_h2(r0.y, r1.y);
            t.z = pack_h2(r0.z, r1.z);
            t.w = pack_h2(r0.w, r1.w);
            *(uint4*)&Bs[kh][c4] = t;
        }
        __syncthreads();

#pragma unroll
        for (int kk = 0; kk < 2; kk++) {        // two k16 steps
            const int kb = kk * 8;
            uint32_t a[4][4], b[4][2];
#pragma unroll
            for (int mt = 0; mt < 4; mt++) {
                int m0 = wr * 64 + mt * 16;
                a[mt][0] = As[m0 + lr    ][kb + lc    ];
                a[mt][1] = As[m0 + lr + 8][kb + lc    ];
                a[mt][2] = As[m0 + lr    ][kb + lc + 4];
                a[mt][3] = As[m0 + lr + 8][kb + lc + 4];
            }
#pragma unroll
            for (int nt = 0; nt < 4; nt++) {
                int n0 = wc * 32 + nt * 8;
                b[nt][0] = Bs[kb + lc    ][n0 + lr];
                b[nt][1] = Bs[kb + lc + 4][n0 + lr];
            }
#pragma unroll
            for (int mt = 0; mt < 4; mt++)
#pragma unroll
                for (int nt = 0; nt < 4; nt++)
                    mma_f16(acc[mt][nt], a[mt], b[nt]);
        }
        __syncthreads();
    }

    // ---- epilogue (same d-layout as m16n8k8) ----
#pragma unroll
    for (int nt = 0; nt < 4; nt++) {
        int cb = wc * 32 + nt * 8 + 2 * lc;
        float bv0 = be[bn0 + cb];
        float bv1 = be[bn0 + cb + 1];
#pragma unroll
        for (int mt = 0; mt < 4; mt++) {
#pragma unroll
            for (int h = 0; h < 2; h++) {
                int lm = wr * 64 + mt * 16 + lr + h * 8;
                float v0 = acc[mt][nt][h * 2 + 0] + bv0;
                float v1 = acc[mt][nt][h * 2 + 1] + bv1;
                if (RELU) { v0 = fmaxf(v0, 0.f); v1 = fmaxf(v1, 0.f); }
                float* dst;
                if (SCATTER) {
                    int token = sRow[lm];
                    if (token >= T_TOK) continue;
                    float g = gte[bm0 + lm];
                    v0 *= g; v1 *= g;
                    dst = Cout + (size_t)token * N + bn0 + cb;
                } else {
                    dst = Ce + (size_t)(bm0 + lm) * N + bn0 + cb;
                }
                *(float2*)dst = make_float2(v0, v1);
            }
        }
    }
}

// ---------------- router logits + gate + ambiguity flagging ----------------
__global__ void router_logits_kernel(const float* __restrict__ r,
                                     const float* __restrict__ wr2,
                                     const float* __restrict__ br2,
                                     int* __restrict__ eid,
                                     float* __restrict__ gate,
                                     int* __restrict__ fixlist,
                                     int* __restrict__ fixcount)
{
    int warp = threadIdx.x >> 5;
    int lane = threadIdx.x & 31;
    int t = blockIdx.x * (blockDim.x >> 5) + warp;
    if (t >= T_TOK) return;

    float acc[E_NUM];
#pragma unroll
    for (int e = 0; e < E_NUM; e++) acc[e] = 0.f;

    const float* row = r + (size_t)t * D_DIM;
    for (int k = lane; k < D_DIM; k += 32) {
        float rv = row[k];
        const float* w = wr2 + (size_t)k * E_NUM;
#pragma unroll
        for (int e = 0; e < E_NUM; e++) acc[e] = fmaf(rv, w[e], acc[e]);
    }
#pragma unroll
    for (int e = 0; e < E_NUM; e++) {
#pragma unroll
        for (int off = 16; off > 0; off >>= 1)
            acc[e] += __shfl_xor_sync(0xFFFFFFFFu, acc[e], off);
    }
    if (lane == 0) {
        float l[E_NUM];
        float m1 = -1e30f, m2 = -1e30f;
        int best = 0;
#pragma unroll
        for (int e = 0; e < E_NUM; e++) {
            l[e] = acc[e] + br2[e];
            if (l[e] > m1) { m2 = m1; m1 = l[e]; best = e; }
            else if (l[e] > m2) m2 = l[e];
        }
        float s = 0.f;
#pragma unroll
        for (int e = 0; e < E_NUM; e++) s += __expf(l[e] - m1);
        eid[t]  = best;
        gate[t] = 1.f / s;
        if (m1 - m2 < GAP_THR) {
            int slot = atomicAdd(fixcount, 1);
            if (slot < FIX_MAX) fixlist[slot] = t;
        }
    }
}

// ---------------- exact fp32 fixup GEMM (BM=32) -> partial logits ----------------
__global__ void __launch_bounds__(256)
fix_gemm_kernel(const float* __restrict__ A, const float* __restrict__ Bmat,
                const float* __restrict__ bias, const float* __restrict__ wr2,
                const int* __restrict__ list, float* __restrict__ fixlogit,
                int N, int K)
{
    constexpr int BM = 32, BN = 128, BK = 16;
    const int bm0 = blockIdx.y * BM;
    const int bn0 = blockIdx.x * BN;
    const int tid = threadIdx.x;
    const int tx = tid & 31;          // col group: 4 cols
    const int ty = tid >> 5;          // row group: 4 rows

    if (list[bm0] >= T_TOK) return;   // whole block is padding

    __shared__ float As[BK][BM];
    __shared__ float Bs[BK][BN];
    __shared__ int   sRow[BM];
    if (tid < BM) sRow[tid] = list[bm0 + tid];
    __syncthreads();

    float acc[4][4];
#pragma unroll
    for (int i = 0; i < 4; i++)
#pragma unroll
        for (int j = 0; j < 4; j++) acc[i][j] = 0.f;

    for (int k0 = 0; k0 < K; k0 += BK) {
        // A tile: 32 x 16 = 128 float4 loads (tid < 128)
        if (tid < 128) {
            int row = tid >> 2;
            int c4  = (tid & 3) * 4;
            int src = sRow[row];
            float4 v = (src < T_TOK)
                ? *(const float4*)(A + (size_t)src * K + k0 + c4)
                : make_float4(0.f, 0.f, 0.f, 0.f);
            As[c4 + 0][row] = v.x;
            As[c4 + 1][row] = v.y;
            As[c4 + 2][row] = v.z;
            As[c4 + 3][row] = v.w;
        }
        // B tile: 16 x 128 = 512 float4 -> 2 iters
#pragma unroll
        for (int l = 0; l < 2; l++) {
            int i4  = tid + l * 256;
            int row = i4 >> 5;
            int c4  = (i4 & 31) * 4;
            *(float4*)(&Bs[row][c4]) =
                *(const float4*)(Bmat + (size_t)(k0 + row) * N + bn0 + c4);
        }
        __syncthreads();
#pragma unroll
        for (int kk = 0; kk < BK; kk++) {
            float a[4], b[4];
            *(float4*)(a) = *(const float4*)(&As[kk][ty * 4]);
            *(float4*)(b) = *(const float4*)(&Bs[kk][tx * 4]);
#pragma unroll
            for (int i = 0; i < 4; i++)
#pragma unroll
                for (int j = 0; j < 4; j++)
                    acc[i][j] = fmaf(a[i], b[j], acc[i][j]);
        }
        __syncthreads();
    }

    float bv[4];
#pragma unroll
    for (int j = 0; j < 4; j++) bv[j] = bias[bn0 + tx * 4 + j];

    float w2r[4][8];
#pragma unroll
    for (int j = 0; j < 4; j++) {
        const float* wrow = wr2 + (size_t)(bn0 + tx * 4 + j) * E_NUM;
        *(float4*)(&w2r[j][0]) = *(const float4*)(wrow);
        *(float4*)(&w2r[j][4]) = *(const float4*)(wrow + 4);
    }

#pragma unroll
    for (int i = 0; i < 4; i++) {
        int lrow = ty * 4 + i;
        if (sRow[lrow] >= T_TOK) continue;
        int slot = bm0 + lrow;
        float o[4];
#pragma unroll
        for (int j = 0; j < 4; j++) o[j] = fmaxf(acc[i][j] + bv[j], 0.f);
        float pl[E_NUM];
#pragma unroll
        for (int e = 0; e < E_NUM; e++) pl[e] = 0.f;
#pragma unroll
        for (int j = 0; j < 4; j++)
#pragma unroll
            for (int e = 0; e < E_NUM; e++)
                pl[e] = fmaf(o[j], w2r[j][e], pl[e]);
#pragma unroll
        for (int e = 0; e < E_NUM; e++)
            atomicAdd(&fixlogit[slot * E_NUM + e], pl[e]);
    }
}

// ---------------- capacity routing (ballot scan, applies fixups first) ----------------
__global__ void route_scan_kernel(const float* __restrict__ fixlogit,
                                  const int* __restrict__ fixlist,
                                  const float* __restrict__ br2,
                                  int* __restrict__ eid,
                                  float* __restrict__ gate,
                                  int* __restrict__ idx,
                                  float* __restrict__ gateslot)
{
    const int e = blockIdx.x;
    const int tid = threadIdx.x;
    const int lane = tid & 31;
    const int w = tid >> 5;

    // phase 0: apply exact-logit corrections (all blocks write identical values)
    for (int s = tid; s < FIX_MAX; s += 256) {
        int t = fixlist[s];
        if (t >= T_TOK) continue;
        float l[E_NUM];
        float m1 = -1e30f;
        int best = 0;
#pragma unroll
        for (int q = 0; q < E_NUM; q++) {
            l[q] = fixlogit[s * E_NUM + q] + br2[q];
            if (l[q] > m1) { m1 = l[q]; best = q; }
        }
        float sum = 0.f;
#pragma unroll
        for (int q = 0; q < E_NUM; q++) sum += __expf(l[q] - m1);
        eid[t]  = best;
        gate[t] = 1.f / sum;
    }
    __syncthreads();

    // phase 1: token-ordered prefix scan via ballot
    __shared__ int wsum[8];
    int base = 0;
    for (int start = 0; start < T_TOK; start += 256) {
        int t = start + tid;
        bool m = (eid[t] == e);
        unsigned bal = __ballot_sync(0xFFFFFFFFu, m);
        if (lane == 0) wsum[w] = __popc(bal);
        __syncthreads();
        int prefix = 0, total = 0;
#pragma unroll
        for (int q = 0; q < 8; q++) {
            int v = wsum[q];
            if (q < w) prefix += v;
            total += v;
        }
        if (m) {
            int p = base + prefix + __popc(bal & ((1u << lane) - 1u));
            if (p < CAP) {
                idx[e * CAP + p]      = t;
                gateslot[e * CAP + p] = gate[t];
            }
        }
        base += total;
        __syncthreads();
    }
}

// ---------------- launch ----------------
extern "C" void kernel_launch(void* const* d_in, const int* in_sizes, int n_in,
                              void* d_out, int out_size)
{
    const float* x   = (const float*)d_in[0];
    const float* wr1 = (const float*)d_in[1];
    const float* br1 = (const float*)d_in[2];
    const float* wr2 = (const float*)d_in[3];
    const float* br2 = (const float*)d_in[4];
    const float* w1  = (const float*)d_in[5];
    const float* b1  = (const float*)d_in[6];
    const float* w2  = (const float*)d_in[7];
    const float* b2  = (const float*)d_in[8];
    float* out = (float*)d_out;

    float *r_ptr, *h_ptr, *gate_ptr, *gs_ptr, *fixlogit_ptr;
    int *eid_ptr, *idx_ptr, *fixlist_ptr, *fixcount_ptr;
    cudaGetSymbolAddress((void**)&r_ptr,        g_r);
    cudaGetSymbolAddress((void**)&h_ptr,        g_h);
    cudaGetSymbolAddress((void**)&fixlogit_ptr, g_fixlogit);
    cudaGetSymbolAddress((void**)&fixlist_ptr,  g_fixlist);
    cudaGetSymbolAddress((void**)&fixcount_ptr, g_fixcount);
    cudaGetSymbolAddress((void**)&gate_ptr,     g_gate);
    cudaGetSymbolAddress((void**)&gs_ptr,       g_gateslot);
    cudaGetSymbolAddress((void**)&eid_ptr,      g_eid);
    cudaGetSymbolAddress((void**)&idx_ptr,      g_idx);

    // 1) zero output + init routing state
    {
        int n4 = ((size_t)T_TOK * D_DIM) / 4;
        zeroinit_kernel<<<(n4 + 255) / 256, 256>>>(
            (float4*)out, n4, idx_ptr, gs_ptr, fixlist_ptr, fixcount_ptr, fixlogit_ptr);
    }

    // 2) r = relu(x @ wr1 + br1)   -- fp16 tensor cores
    {
        dim3 grid(D_DIM / 128, T_TOK / 128, 1);
        h16gemm_kernel<false, true, false><<<grid, 256>>>(
            x, wr1, br1, r_ptr, D_DIM, D_DIM,
            nullptr, nullptr, 0, 0, 0, 0);
    }

    // 3) logits -> eid, gate, flag ambiguous tokens
    router_logits_kernel<<<T_TOK / 8, 256>>>(r_ptr, wr2, br2, eid_ptr, gate_ptr,
                                             fixlist_ptr, fixcount_ptr);

    // 4) exact fp32 partial logits for flagged tokens (BM=32, high parallelism)
    {
        dim3 grid(D_DIM / 128, FIX_MAX / 32, 1);
        fix_gemm_kernel<<<grid, 256>>>(x, wr1, br1, wr2, fixlist_ptr,
                                       fixlogit_ptr, D_DIM, D_DIM);
    }

    // 5) apply fixups + routing scan (ballot-based)
    route_scan_kernel<<<E_NUM, 256>>>(fixlogit_ptr, fixlist_ptr, br2,
                                      eid_ptr, gate_ptr, idx_ptr, gs_ptr);

    // 6) h[e] = relu(gather(x, idx[e]) @ w1[e] + b1[e])   -- fp16
    {
        dim3 grid(H_DIM / 128, CAP / 128, E_NUM);
        h16gemm_kernel<true, true, false><<<grid, 256>>>(
            x, w1, b1, h_ptr, H_DIM, D_DIM,
            idx_ptr, nullptr,
            0, (size_t)D_DIM * H_DIM, H_DIM, (size_t)CAP * H_DIM);
    }

    // 7) out[idx] = gate * (h[e] @ w2[e] + b2[e])   -- fp16
    {
        dim3 grid(D_DIM / 128, CAP / 128, E_NUM);
        h16gemm_kernel<false, false, true><<<grid, 256>>>(
            h_ptr, w2, b2, out, D_DIM, H_DIM,
            idx_ptr, gs_ptr,
            (size_t)CAP * H_DIM, (size_t)H_DIM * D_DIM, D_DIM, 0);
    }
}

// round 7
// speedup vs baseline: 2.1718x; 1.1523x over previous
#include <cuda_runtime.h>
#include <cuda_fp16.h>
#include <cstdint>

#define T_TOK 16384
#define D_DIM 1024
#define E_NUM 8
#define H_DIM 4096
#define CAP   (T_TOK / E_NUM)   // 2048
#define FIX_MAX 2048
#define GAP_THR 0.005f

// ---------------- scratch (device globals: allocation-free) ----------------
__device__ __half g_xh[(size_t)T_TOK * D_DIM];          // x fp16          32MB
__device__ __half g_wr1h[(size_t)D_DIM * D_DIM];        // wr1 fp16         2MB
__device__ __half g_w1h[(size_t)E_NUM * D_DIM * H_DIM]; // w1 fp16         64MB
__device__ __half g_w2h[(size_t)E_NUM * H_DIM * D_DIM]; // w2 fp16         64MB
__device__ float  g_r[(size_t)T_TOK * D_DIM];           // router hidden   64MB
__device__ __half g_h[(size_t)E_NUM * CAP * H_DIM];     // expert hidden  128MB
__device__ float  g_fixlogit[FIX_MAX * E_NUM];
__device__ int    g_fixlist[FIX_MAX];
__device__ int    g_fixcount;
__device__ int    g_eid[T_TOK];
__device__ float  g_gate[T_TOK];
__device__ int    g_idx[E_NUM * CAP];
__device__ float  g_gateslot[E_NUM * CAP];

// ---------------- helpers ----------------
__device__ __forceinline__ uint32_t pack_h2(float a, float b) {
    __half2 h = __floats2half2_rn(a, b);
    return *(uint32_t*)&h;
}
__device__ __forceinline__ void mma_f16(float* d, const uint32_t* a,
                                        const uint32_t* b) {
    asm volatile(
        "mma.sync.aligned.m16n8k16.row.col.f32.f16.f16.f32 "
        "{%0,%1,%2,%3}, {%4,%5,%6,%7}, {%8,%9}, {%0,%1,%2,%3};"
        : "+f"(d[0]), "+f"(d[1]), "+f"(d[2]), "+f"(d[3])
        : "r"(a[0]), "r"(a[1]), "r"(a[2]), "r"(a[3]),
          "r"(b[0]), "r"(b[1]));
}

// ---------------- zero/init ----------------
__global__ void zeroinit_kernel(float4* out, int n4, int* idx, float* gs,
                                int* fixlist, int* fixcount, float* fixlogit) {
    int i = blockIdx.x * blockDim.x + threadIdx.x;
    if (i < n4) out[i] = make_float4(0.f, 0.f, 0.f, 0.f);
    if (i < E_NUM * CAP) { idx[i] = T_TOK; gs[i] = 0.f; }
    if (i < FIX_MAX) fixlist[i] = T_TOK;
    if (i < FIX_MAX * E_NUM) fixlogit[i] = 0.f;
    if (i == 0) *fixcount = 0;
}

// ---------------- fp32 -> fp16 staging ----------------
__global__ void f2h_kernel(const float4* __restrict__ in,
                           uint2* __restrict__ out, int n4) {
    int i = blockIdx.x * blockDim.x + threadIdx.x;
    if (i < n4) {
        float4 v = in[i];
        uint2 o;
        o.x = pack_h2(v.x, v.y);
        o.y = pack_h2(v.z, v.w);
        out[i] = o;
    }
}

// ---------------- FP16 tensor-core GEMM (m16n8k16, fp32 accum) ----------------
// C[M,N] = op(A[M,K] @ B[K,N] + bias[N]); A,B pre-staged fp16.
// GATHER:  A row m is A[idx[m]] (idx==T_TOK -> zero row)
// SCATTER: output row m goes to Cout[idx[m]]*gate[m] (fp32); idx==T_TOK skipped
// OUTH:    write output as fp16 (hidden for next GEMM)
template<bool GATHER, bool RELU, bool SCATTER, bool OUTH>
__global__ void __launch_bounds__(256)
h16gemm_kernel(const __half* __restrict__ A, const __half* __restrict__ Bmat,
               const float* __restrict__ bias, void* __restrict__ CoutV,
               int N, int K,
               const int* __restrict__ rowidx, const float* __restrict__ gates,
               size_t sA, size_t sB, size_t sBias, size_t sC)
{
    constexpr int BM = 128, BN = 128, BK = 32;
    constexpr int KH = BK / 2;               // 16 k-pairs

    const int e = blockIdx.z;
    const __half* Ae  = A    + (size_t)e * sA;
    const __half* Be  = Bmat + (size_t)e * sB;
    const float*  be  = bias + (size_t)e * sBias;
    const int*   idxe = (GATHER || SCATTER) ? rowidx + e * CAP : nullptr;
    const float* gte  = SCATTER ? gates + e * CAP : nullptr;

    const int bm0 = blockIdx.y * BM;
    const int bn0 = blockIdx.x * BN;
    const int tid = threadIdx.x;
    const int warp = tid >> 5;
    const int lane = tid & 31;
    const int wr = warp >> 2;      // 0..1  (64-row slabs)
    const int wc = warp & 3;       // 0..3  (32-col slabs)
    const int lr = lane >> 2;      // 0..7
    const int lc = lane & 3;       // 0..3

    __shared__ uint32_t As[BM][KH + 4];    // word = half2(k even, k odd)
    __shared__ uint32_t Bs[KH][BN + 8];    // word = half2(B[2kh][n], B[2kh+1][n])
    __shared__ int      sRow[BM];

    if (tid < BM) {
        sRow[tid] = (GATHER || SCATTER) ? idxe[bm0 + tid] : (bm0 + tid);
    }
    __syncthreads();

    float acc[4][4][4];
#pragma unroll
    for (int mt = 0; mt < 4; mt++)
#pragma unroll
        for (int nt = 0; nt < 4; nt++)
#pragma unroll
            for (int i = 0; i < 4; i++) acc[mt][nt][i] = 0.f;

    for (int k0 = 0; k0 < K; k0 += BK) {
        // ---- A tile: 128 rows x 32 k (fp16 direct copy) ----
#pragma unroll
        for (int l = 0; l < 2; l++) {
            int i = tid + l * 256;              // 0..511
            int row = i >> 2;                   // 0..127
            int kq  = (i & 3) * 4;              // word base: 0,4,8,12
            uint4 t;
            if (GATHER) {
                int src = sRow[row];
                if (src >= T_TOK) t = make_uint4(0u, 0u, 0u, 0u);
                else t = *(const uint4*)(Ae + (size_t)src * K + k0 + kq * 2);
            } else {
                t = *(const uint4*)(Ae + (size_t)(bm0 + row) * K + k0 + kq * 2);
            }
            *(uint4*)&As[row][kq] = t;
        }
        // ---- B tile: 32 k x 128 n, interleave k-pairs via byte_perm ----
#pragma unroll
        for (int l = 0; l < 2; l++) {
            int i = tid + l * 256;              // 0..511
            int kh = i >> 5;                    // 0..15
            int c4 = (i & 31) * 4;              // 0..124
            const __half* p0 = Be + (size_t)(k0 + 2 * kh)     * N + bn0 + c4;
            const __half* p1 = Be + (size_t)(k0 + 2 * kh + 1) * N + bn0 + c4;
            uint2 r0 = *(const uint2*)p0;       // 4 halfs of row 2kh
            uint2 r1 = *(const uint2*)p1;       // 4 halfs of row 2kh+1
            uint4 t;
            t.x = __byte_perm(r0.x, r1.x, 0x5410);
            t.y = __byte_perm(r0.x, r1.x, 0x7632);
            t.z = __byte_perm(r0.y, r1.y, 0x5410);
            t.w = __byte_perm(r0.y, r1.y, 0x7632);
            *(uint4*)&Bs[kh][c4] = t;
        }
        __syncthreads();

#pragma unroll
        for (int kk = 0; kk < 2; kk++) {        // two k16 steps
            const int kb = kk * 8;
            uint32_t a[4][4], b[4][2];
#pragma unroll
            for (int mt = 0; mt < 4; mt++) {
                int m0 = wr * 64 + mt * 16;
                a[mt][0] = As[m0 + lr    ][kb + lc    ];
                a[mt][1] = As[m0 + lr + 8][kb + lc    ];
                a[mt][2] = As[m0 + lr    ][kb + lc + 4];
                a[mt][3] = As[m0 + lr + 8][kb + lc + 4];
            }
#pragma unroll
            for (int nt = 0; nt < 4; nt++) {
                int n0 = wc * 32 + nt * 8;
                b[nt][0] = Bs[kb + lc    ][n0 + lr];
                b[nt][1] = Bs[kb + lc + 4][n0 + lr];
            }
#pragma unroll
            for (int mt = 0; mt < 4; mt++)
#pragma unroll
                for (int nt = 0; nt < 4; nt++)
                    mma_f16(acc[mt][nt], a[mt], b[nt]);
        }
        __syncthreads();
    }

    // ---- epilogue ----
#pragma unroll
    for (int nt = 0; nt < 4; nt++) {
        int cb = wc * 32 + nt * 8 + 2 * lc;
        float bv0 = be[bn0 + cb];
        float bv1 = be[bn0 + cb + 1];
#pragma unroll
        for (int mt = 0; mt < 4; mt++) {
#pragma unroll
            for (int h = 0; h < 2; h++) {
                int lm = wr * 64 + mt * 16 + lr + h * 8;
                float v0 = acc[mt][nt][h * 2 + 0] + bv0;
                float v1 = acc[mt][nt][h * 2 + 1] + bv1;
                if (RELU) { v0 = fmaxf(v0, 0.f); v1 = fmaxf(v1, 0.f); }
                if (SCATTER) {
                    int token = sRow[lm];
                    if (token >= T_TOK) continue;
                    float g = gte[bm0 + lm];
                    v0 *= g; v1 *= g;
                    float* dst = (float*)CoutV + (size_t)token * N + bn0 + cb;
                    *(float2*)dst = make_float2(v0, v1);
                } else if (OUTH) {
                    __half* dst = (__half*)CoutV + (size_t)e * sC
                                  + (size_t)(bm0 + lm) * N + bn0 + cb;
                    *(uint32_t*)dst = pack_h2(v0, v1);
                } else {
                    float* dst = (float*)CoutV + (size_t)e * sC
                                 + (size_t)(bm0 + lm) * N + bn0 + cb;
                    *(float2*)dst = make_float2(v0, v1);
                }
            }
        }
    }
}

// ---------------- router logits + gate + ambiguity flagging ----------------
__global__ void router_logits_kernel(const float* __restrict__ r,
                                     const float* __restrict__ wr2,
                                     const float* __restrict__ br2,
                                     int* __restrict__ eid,
                                     float* __restrict__ gate,
                                     int* __restrict__ fixlist,
                                     int* __restrict__ fixcount)
{
    int warp = threadIdx.x >> 5;
    int lane = threadIdx.x & 31;
    int t = blockIdx.x * (blockDim.x >> 5) + warp;
    if (t >= T_TOK) return;

    float acc[E_NUM];
#pragma unroll
    for (int e = 0; e < E_NUM; e++) acc[e] = 0.f;

    const float* row = r + (size_t)t * D_DIM;
    for (int k = lane; k < D_DIM; k += 32) {
        float rv = row[k];
        const float* w = wr2 + (size_t)k * E_NUM;
#pragma unroll
        for (int e = 0; e < E_NUM; e++) acc[e] = fmaf(rv, w[e], acc[e]);
    }
#pragma unroll
    for (int e = 0; e < E_NUM; e++) {
#pragma unroll
        for (int off = 16; off > 0; off >>= 1)
            acc[e] += __shfl_xor_sync(0xFFFFFFFFu, acc[e], off);
    }
    if (lane == 0) {
        float l[E_NUM];
        float m1 = -1e30f, m2 = -1e30f;
        int best = 0;
#pragma unroll
        for (int e = 0; e < E_NUM; e++) {
            l[e] = acc[e] + br2[e];
            if (l[e] > m1) { m2 = m1; m1 = l[e]; best = e; }
            else if (l[e] > m2) m2 = l[e];
        }
        float s = 0.f;
#pragma unroll
        for (int e = 0; e < E_NUM; e++) s += __expf(l[e] - m1);
        eid[t]  = best;
        gate[t] = 1.f / s;
        if (m1 - m2 < GAP_THR) {
            int slot = atomicAdd(fixcount, 1);
            if (slot < FIX_MAX) fixlist[slot] = t;
        }
    }
}

// ---------------- exact fp32 fixup GEMM (BM=32) -> partial logits ----------------
__global__ void __launch_bounds__(256)
fix_gemm_kernel(const float* __restrict__ A, const float* __restrict__ Bmat,
                const float* __restrict__ bias, const float* __restrict__ wr2,
                const int* __restrict__ list, float* __restrict__ fixlogit,
                int N, int K)
{
    constexpr int BM = 32, BN = 128, BK = 16;
    const int bm0 = blockIdx.y * BM;
    const int bn0 = blockIdx.x * BN;
    const int tid = threadIdx.x;
    const int tx = tid & 31;
    const int ty = tid >> 5;

    if (list[bm0] >= T_TOK) return;   // whole block is padding

    __shared__ float As[BK][BM];
    __shared__ float Bs[BK][BN];
    __shared__ int   sRow[BM];
    if (tid < BM) sRow[tid] = list[bm0 + tid];
    __syncthreads();

    float acc[4][4];
#pragma unroll
    for (int i = 0; i < 4; i++)
#pragma unroll
        for (int j = 0; j < 4; j++) acc[i][j] = 0.f;

    for (int k0 = 0; k0 < K; k0 += BK) {
        if (tid < 128) {
            int row = tid >> 2;
            int c4  = (tid & 3) * 4;
            int src = sRow[row];
            float4 v = (src < T_TOK)
                ? *(const float4*)(A + (size_t)src * K + k0 + c4)
                : make_float4(0.f, 0.f, 0.f, 0.f);
            As[c4 + 0][row] = v.x;
            As[c4 + 1][row] = v.y;
            As[c4 + 2][row] = v.z;
            As[c4 + 3][row] = v.w;
        }
#pragma unroll
        for (int l = 0; l < 2; l++) {
            int i4  = tid + l * 256;
            int row = i4 >> 5;
            int c4  = (i4 & 31) * 4;
            *(float4*)(&Bs[row][c4]) =
                *(const float4*)(Bmat + (size_t)(k0 + row) * N + bn0 + c4);
        }
        __syncthreads();
#pragma unroll
        for (int kk = 0; kk < BK; kk++) {
            float a[4], b[4];
            *(float4*)(a) = *(const float4*)(&As[kk][ty * 4]);
            *(float4*)(b) = *(const float4*)(&Bs[kk][tx * 4]);
#pragma unroll
            for (int i = 0; i < 4; i++)
#pragma unroll
                for (int j = 0; j < 4; j++)
                    acc[i][j] = fmaf(a[i], b[j], acc[i][j]);
        }
        __syncthreads();
    }

    float bv[4];
#pragma unroll
    for (int j = 0; j < 4; j++) bv[j] = bias[bn0 + tx * 4 + j];

    float w2r[4][8];
#pragma unroll
    for (int j = 0; j < 4; j++) {
        const float* wrow = wr2 + (size_t)(bn0 + tx * 4 + j) * E_NUM;
        *(float4*)(&w2r[j][0]) = *(const float4*)(wrow);
        *(float4*)(&w2r[j][4]) = *(const float4*)(wrow + 4);
    }

#pragma unroll
    for (int i = 0; i < 4; i++) {
        int lrow = ty * 4 + i;
        if (sRow[lrow] >= T_TOK) continue;
        int slot = bm0 + lrow;
        float o[4];
#pragma unroll
        for (int j = 0; j < 4; j++) o[j] = fmaxf(acc[i][j] + bv[j], 0.f);
        float pl[E_NUM];
#pragma unroll
        for (int e = 0; e < E_NUM; e++) pl[e] = 0.f;
#pragma unroll
        for (int j = 0; j < 4; j++)
#pragma unroll
            for (int e = 0; e < E_NUM; e++)
                pl[e] = fmaf(o[j], w2r[j][e], pl[e]);
#pragma unroll
        for (int e = 0; e < E_NUM; e++)
            atomicAdd(&fixlogit[slot * E_NUM + e], pl[e]);
    }
}

// ---------------- capacity routing (ballot scan, applies fixups first) ----------------
__global__ void route_scan_kernel(const float* __restrict__ fixlogit,
                                  const int* __restrict__ fixlist,
                                  const float* __restrict__ br2,
                                  int* __restrict__ eid,
                                  float* __restrict__ gate,
                                  int* __restrict__ idx,
                                  float* __restrict__ gateslot)
{
    const int e = blockIdx.x;
    const int tid = threadIdx.x;
    const int lane = tid & 31;
    const int w = tid >> 5;

    for (int s = tid; s < FIX_MAX; s += 256) {
        int t = fixlist[s];
        if (t >= T_TOK) continue;
        float l[E_NUM];
        float m1 = -1e30f;
        int best = 0;
#pragma unroll
        for (int q = 0; q < E_NUM; q++) {
            l[q] = fixlogit[s * E_NUM + q] + br2[q];
            if (l[q] > m1) { m1 = l[q]; best = q; }
        }
        float sum = 0.f;
#pragma unroll
        for (int q = 0; q < E_NUM; q++) sum += __expf(l[q] - m1);
        eid[t]  = best;
        gate[t] = 1.f / sum;
    }
    __syncthreads();

    __shared__ int wsum[8];
    int base = 0;
    for (int start = 0; start < T_TOK; start += 256) {
        int t = start + tid;
        bool m = (eid[t] == e);
        unsigned bal = __ballot_sync(0xFFFFFFFFu, m);
        if (lane == 0) wsum[w] = __popc(bal);
        __syncthreads();
        int prefix = 0, total = 0;
#pragma unroll
        for (int q = 0; q < 8; q++) {
            int v = wsum[q];
            if (q < w) prefix += v;
            total += v;
        }
        if (m) {
            int p = base + prefix + __popc(bal & ((1u << lane) - 1u));
            if (p < CAP) {
                idx[e * CAP + p]      = t;
                gateslot[e * CAP + p] = gate[t];
            }
        }
        base += total;
        __syncthreads();
    }
}

// ---------------- launch ----------------
extern "C" void kernel_launch(void* const* d_in, const int* in_sizes, int n_in,
                              void* d_out, int out_size)
{
    const float* x   = (const float*)d_in[0];
    const float* wr1 = (const float*)d_in[1];
    const float* br1 = (const float*)d_in[2];
    const float* wr2 = (const float*)d_in[3];
    const float* br2 = (const float*)d_in[4];
    const float* w1  = (const float*)d_in[5];
    const float* b1  = (const float*)d_in[6];
    const float* w2  = (const float*)d_in[7];
    const float* b2  = (const float*)d_in[8];
    float* out = (float*)d_out;

    __half *xh_ptr, *wr1h_ptr, *w1h_ptr, *w2h_ptr, *h_ptr;
    float *r_ptr, *gate_ptr, *gs_ptr, *fixlogit_ptr;
    int *eid_ptr, *idx_ptr, *fixlist_ptr, *fixcount_ptr;
    cudaGetSymbolAddress((void**)&xh_ptr,       g_xh);
    cudaGetSymbolAddress((void**)&wr1h_ptr,     g_wr1h);
    cudaGetSymbolAddress((void**)&w1h_ptr,      g_w1h);
    cudaGetSymbolAddress((void**)&w2h_ptr,      g_w2h);
    cudaGetSymbolAddress((void**)&r_ptr,        g_r);
    cudaGetSymbolAddress((void**)&h_ptr,        g_h);
    cudaGetSymbolAddress((void**)&fixlogit_ptr, g_fixlogit);
    cudaGetSymbolAddress((void**)&fixlist_ptr,  g_fixlist);
    cudaGetSymbolAddress((void**)&fixcount_ptr, g_fixcount);
    cudaGetSymbolAddress((void**)&gate_ptr,     g_gate);
    cudaGetSymbolAddress((void**)&gs_ptr,       g_gateslot);
    cudaGetSymbolAddress((void**)&eid_ptr,      g_eid);
    cudaGetSymbolAddress((void**)&idx_ptr,      g_idx);

    // 1) zero output + init routing state
    {
        int n4 = ((size_t)T_TOK * D_DIM) / 4;
        zeroinit_kernel<<<(n4 + 255) / 256, 256>>>(
            (float4*)out, n4, idx_ptr, gs_ptr, fixlist_ptr, fixcount_ptr, fixlogit_ptr);
    }

    // 2) fp16 staging (one pass each)
    {
        int n4;
        n4 = (T_TOK * D_DIM) / 4;
        f2h_kernel<<<(n4 + 255) / 256, 256>>>((const float4*)x, (uint2*)xh_ptr, n4);
        n4 = (D_DIM * D_DIM) / 4;
        f2h_kernel<<<(n4 + 255) / 256, 256>>>((const float4*)wr1, (uint2*)wr1h_ptr, n4);
        n4 = (E_NUM * D_DIM * H_DIM) / 4;
        f2h_kernel<<<(n4 + 255) / 256, 256>>>((const float4*)w1, (uint2*)w1h_ptr, n4);
        n4 = (E_NUM * H_DIM * D_DIM) / 4;
        f2h_kernel<<<(n4 + 255) / 256, 256>>>((const float4*)w2, (uint2*)w2h_ptr, n4);
    }

    // 3) r = relu(x @ wr1 + br1)   -- fp16 tensor cores, fp32 out
    {
        dim3 grid(D_DIM / 128, T_TOK / 128, 1);
        h16gemm_kernel<false, true, false, false><<<grid, 256>>>(
            xh_ptr, wr1h_ptr, br1, r_ptr, D_DIM, D_DIM,
            nullptr, nullptr, 0, 0, 0, 0);
    }

    // 4) logits -> eid, gate, flag ambiguous tokens
    router_logits_kernel<<<T_TOK / 8, 256>>>(r_ptr, wr2, br2, eid_ptr, gate_ptr,
                                             fixlist_ptr, fixcount_ptr);

    // 5) exact fp32 partial logits for flagged tokens
    {
        dim3 grid(D_DIM / 128, FIX_MAX / 32, 1);
        fix_gemm_kernel<<<grid, 256>>>(x, wr1, br1, wr2, fixlist_ptr,
                                       fixlogit_ptr, D_DIM, D_DIM);
    }

    // 6) apply fixups + routing scan
    route_scan_kernel<<<E_NUM, 256>>>(fixlogit_ptr, fixlist_ptr, br2,
                                      eid_ptr, gate_ptr, idx_ptr, gs_ptr);

    // 7) h[e] = relu(gather(xh, idx[e]) @ w1h[e] + b1[e])  -> fp16 hidden
    {
        dim3 grid(H_DIM / 128, CAP / 128, E_NUM);
        h16gemm_kernel<true, true, false, true><<<grid, 256>>>(
            xh_ptr, w1h_ptr, b1, h_ptr, H_DIM, D_DIM,
            idx_ptr, nullptr,
            0, (size_t)D_DIM * H_DIM, H_DIM, (size_t)CAP * H_DIM);
    }

    // 8) out[idx] = gate * (h[e] @ w2h[e] + b2[e])
    {
        dim3 grid(D_DIM / 128, CAP / 128, E_NUM);
        h16gemm_kernel<false, false, true, false><<<grid, 256>>>(
            h_ptr, w2h_ptr, b2, out, D_DIM, H_DIM,
            idx_ptr, gs_ptr,
            (size_t)CAP * H_DIM, (size_t)H_DIM * D_DIM, D_DIM, 0);
    }
}